// round 1
// baseline (speedup 1.0000x reference)
#include <cuda_runtime.h>
#include <cuda_bf16.h>

// SSIM loss, fused single-pass tiled kernel + tiny finalize kernel.
// img shapes: (16, 3, 512, 512) fp32. Output: scalar fp32 = 1 - mean(ssim_map).

#define IMG     512
#define NIMG    48              // 16 * 3
#define TX      64
#define TY      32
#define HALO    5
#define IW      (TX + 2*HALO)   // 74
#define IH      (TY + 2*HALO)   // 42
#define NT      256
#define GXB     (IMG/TX)        // 8
#define GYB     (IMG/TY)        // 16
#define NBLOCKS (GXB*GYB*NIMG)  // 6144

// Normalized 1-D Gaussian taps (sigma=1.5, window 11). Outer product of the
// normalized 1-D kernel == normalized 2-D kernel used by the reference.
__device__ __constant__ const float W_[11] = {
    0.00102838f, 0.00759876f, 0.03600077f, 0.10936070f, 0.21300554f,
    0.26601173f,
    0.21300554f, 0.10936070f, 0.03600077f, 0.00759876f, 0.00102838f
};
// constexpr copy so the compiler can inline taps as immediates
#define W0 0.00102838f
#define W1 0.00759876f
#define W2 0.03600077f
#define W3 0.10936070f
#define W4 0.21300554f
#define W5 0.26601173f

__device__ float g_partials[NBLOCKS];

__global__ __launch_bounds__(NT, 2)
void ssim_tile_kernel(const float* __restrict__ img1,
                      const float* __restrict__ img2)
{
    extern __shared__ float smem[];
    float* s1 = smem;                    // [IH][IW]
    float* s2 = s1 + IH * IW;            // [IH][IW]
    float* h  = s2 + IH * IW;            // [5][IH][TX]

    const int tid = threadIdx.x;
    const int bz  = blockIdx.z;                       // image index (n*3+c)
    const float* base1 = img1 + (size_t)bz * IMG * IMG;
    const float* base2 = img2 + (size_t)bz * IMG * IMG;

    const int gx0 = blockIdx.x * TX - HALO;
    const int gy0 = blockIdx.y * TY - HALO;

    // ---- load raw tiles (zero-padded at image borders) ----
    for (int idx = tid; idx < IH * IW; idx += NT) {
        int r = idx / IW;
        int c = idx - r * IW;
        int gy = gy0 + r;
        int gx = gx0 + c;
        bool ok = ((unsigned)gy < (unsigned)IMG) && ((unsigned)gx < (unsigned)IMG);
        int g = gy * IMG + gx;
        s1[idx] = ok ? __ldg(base1 + g) : 0.0f;
        s2[idx] = ok ? __ldg(base2 + g) : 0.0f;
    }
    __syncthreads();

    // ---- horizontal pass: 5 channels (x, y, x^2, y^2, xy) ----
    const float Wt[11] = {W0, W1, W2, W3, W4, W5, W4, W3, W2, W1, W0};
    for (int idx = tid; idx < IH * TX; idx += NT) {
        int r = idx >> 6;          // /TX
        int c = idx & (TX - 1);
        const float* p1 = s1 + r * IW + c;
        const float* p2 = s2 + r * IW + c;
        float a1 = 0.f, a2 = 0.f, a3 = 0.f, a4 = 0.f, a5 = 0.f;
        #pragma unroll
        for (int k = 0; k < 11; k++) {
            float x = p1[k];
            float y = p2[k];
            float wx = Wt[k] * x;
            float wy = Wt[k] * y;
            a1 = fmaf(Wt[k], x, a1);
            a2 = fmaf(Wt[k], y, a2);
            a3 = fmaf(wx, x, a3);
            a4 = fmaf(wy, y, a4);
            a5 = fmaf(wx, y, a5);
        }
        h[0 * IH * TX + idx] = a1;
        h[1 * IH * TX + idx] = a2;
        h[2 * IH * TX + idx] = a3;
        h[3 * IH * TX + idx] = a4;
        h[4 * IH * TX + idx] = a5;
    }
    __syncthreads();

    // ---- vertical pass + pointwise SSIM + per-thread accumulation ----
    const float C1 = 0.01f * 0.01f;
    const float C2 = 0.03f * 0.03f;
    float acc = 0.f;
    for (int idx = tid; idx < TX * TY; idx += NT) {
        int r = idx >> 6;          // /TX
        int c = idx & (TX - 1);
        const float* q0 = h + 0 * IH * TX + r * TX + c;
        const float* q1 = h + 1 * IH * TX + r * TX + c;
        const float* q2 = h + 2 * IH * TX + r * TX + c;
        const float* q3 = h + 3 * IH * TX + r * TX + c;
        const float* q4 = h + 4 * IH * TX + r * TX + c;
        float b1 = 0.f, b2 = 0.f, b3 = 0.f, b4 = 0.f, b5 = 0.f;
        #pragma unroll
        for (int k = 0; k < 11; k++) {
            b1 = fmaf(Wt[k], q0[k * TX], b1);
            b2 = fmaf(Wt[k], q1[k * TX], b2);
            b3 = fmaf(Wt[k], q2[k * TX], b3);
            b4 = fmaf(Wt[k], q3[k * TX], b4);
            b5 = fmaf(Wt[k], q4[k * TX], b5);
        }
        float mu1 = b1, mu2 = b2;
        float mu1sq = mu1 * mu1;
        float mu2sq = mu2 * mu2;
        float mu12  = mu1 * mu2;
        float sg1 = b3 - mu1sq;
        float sg2 = b4 - mu2sq;
        float sg12 = b5 - mu12;
        float num = (2.0f * mu12 + C1) * (2.0f * sg12 + C2);
        float den = (mu1sq + mu2sq + C1) * (sg1 + sg2 + C2);
        acc += num / den;
    }

    // ---- block reduction (deterministic) ----
    #pragma unroll
    for (int off = 16; off > 0; off >>= 1)
        acc += __shfl_xor_sync(0xFFFFFFFFu, acc, off);

    __shared__ float warpsum[NT / 32];
    if ((tid & 31) == 0) warpsum[tid >> 5] = acc;
    __syncthreads();
    if (tid == 0) {
        float s = 0.f;
        #pragma unroll
        for (int i = 0; i < NT / 32; i++) s += warpsum[i];
        int bid = blockIdx.x + GXB * (blockIdx.y + GYB * blockIdx.z);
        g_partials[bid] = s;
    }
}

__global__ void ssim_finalize_kernel(float* __restrict__ out)
{
    __shared__ double sd[256];
    double s = 0.0;
    for (int i = threadIdx.x; i < NBLOCKS; i += 256)
        s += (double)g_partials[i];
    sd[threadIdx.x] = s;
    __syncthreads();
    for (int st = 128; st > 0; st >>= 1) {
        if (threadIdx.x < st) sd[threadIdx.x] += sd[threadIdx.x + st];
        __syncthreads();
    }
    if (threadIdx.x == 0) {
        const double N = 16.0 * 3.0 * 512.0 * 512.0;
        out[0] = (float)(1.0 - sd[0] / N);
    }
}

extern "C" void kernel_launch(void* const* d_in, const int* in_sizes, int n_in,
                              void* d_out, int out_size)
{
    const float* img1 = (const float*)d_in[0];
    const float* img2 = (const float*)d_in[1];
    float* out = (float*)d_out;

    const int smem_bytes = (2 * IH * IW + 5 * IH * TX) * (int)sizeof(float); // 78624
    cudaFuncSetAttribute(ssim_tile_kernel,
                         cudaFuncAttributeMaxDynamicSharedMemorySize, smem_bytes);

    dim3 grid(GXB, GYB, NIMG);
    ssim_tile_kernel<<<grid, NT, smem_bytes>>>(img1, img2);
    ssim_finalize_kernel<<<1, 256>>>(out);
}

// round 2
// speedup vs baseline: 1.4345x; 1.4345x over previous
#include <cuda_runtime.h>
#include <cuda_bf16.h>

// SSIM loss: fused separable 11x11 Gaussian SSIM, register-strip version.
// imgs (16,3,512,512) fp32 -> scalar fp32 = 1 - mean(ssim_map).

#define IMG     512
#define NIMG    48
#define TX      64
#define TY      32
#define HALO    5
#define IW      74              // TX + 10
#define IWP     75              // padded stride (conflict-free: 75 mod 32 = 11, coprime)
#define IH      42              // TY + 10
#define HP      65              // H row stride (65 mod 32 = 1 -> row-distinct banks)
#define HCH     (IH*HP)         // 2730, channel stride in H
#define NT      384
#define GXB     (IMG/TX)        // 8
#define GYB     (IMG/TY)        // 16
#define NBLOCKS (GXB*GYB*NIMG)  // 6144

#define W0 0.00102838f
#define W1 0.00759876f
#define W2 0.03600077f
#define W3 0.10936070f
#define W4 0.21300554f
#define W5 0.26601173f

__device__ float4 g_partials4[NBLOCKS / 4];

__global__ __launch_bounds__(NT, 2)
void ssim_tile_kernel(const float* __restrict__ img1,
                      const float* __restrict__ img2)
{
    extern __shared__ float smem[];
    float* s1 = smem;               // [IH][IWP]  3150
    float* s2 = s1 + IH * IWP;      // 3150
    float* H  = s2 + IH * IWP;      // [5][IH][HP] 13650

    const int tid = threadIdx.x;
    const int bz  = blockIdx.z;
    const float* base1 = img1 + (size_t)bz * IMG * IMG;
    const float* base2 = img2 + (size_t)bz * IMG * IMG;

    const int gx0 = blockIdx.x * TX - HALO;
    const int gy0 = blockIdx.y * TY - HALO;

    const float Wt[11] = {W0, W1, W2, W3, W4, W5, W4, W3, W2, W1, W0};

    // ---- stage 0: load raw tiles, zero-padded ----
    for (int idx = tid; idx < IH * IW; idx += NT) {
        int r = idx / IW;
        int c = idx - r * IW;
        int gy = gy0 + r;
        int gx = gx0 + c;
        bool ok = ((unsigned)gy < (unsigned)IMG) && ((unsigned)gx < (unsigned)IMG);
        int g = gy * IMG + gx;
        s1[r * IWP + c] = ok ? __ldg(base1 + g) : 0.0f;
        s2[r * IWP + c] = ok ? __ldg(base2 + g) : 0.0f;
    }
    __syncthreads();

    // ---- pass 1: horizontal blur of (x, y, x2, y2, xy), strips of 8 cols ----
    // 336 strips = 42 rows * 8 column-groups; one per thread (NT=384).
    if (tid < IH * (TX / 8)) {
        int row = tid % IH;
        int cs  = (tid / IH) * 8;
        const float* p1 = s1 + row * IWP + cs;
        const float* p2 = s2 + row * IWP + cs;

        float a0[8], a1[8], a2[8], a3[8], a4[8];
        #pragma unroll
        for (int o = 0; o < 8; o++) { a0[o]=0.f; a1[o]=0.f; a2[o]=0.f; a3[o]=0.f; a4[o]=0.f; }

        #pragma unroll
        for (int e = 0; e < 18; e++) {
            float x = p1[e];
            float y = p2[e];
            float xx = x * x;
            float yy = y * y;
            float xy = x * y;
            const int olo = (e >= 10) ? (e - 10) : 0;
            const int ohi = (e < 8) ? e : 7;
            #pragma unroll
            for (int o = olo; o <= ohi; o++) {
                const float w = Wt[e - o];       // compile-time immediate
                a0[o] = fmaf(w, x,  a0[o]);
                a1[o] = fmaf(w, y,  a1[o]);
                a2[o] = fmaf(w, xx, a2[o]);
                a3[o] = fmaf(w, yy, a3[o]);
                a4[o] = fmaf(w, xy, a4[o]);
            }
        }
        float* hp = H + row * HP + cs;
        #pragma unroll
        for (int o = 0; o < 8; o++) {
            hp[0*HCH + o] = a0[o];
            hp[1*HCH + o] = a1[o];
            hp[2*HCH + o] = a2[o];
            hp[3*HCH + o] = a3[o];
            hp[4*HCH + o] = a4[o];
        }
    }
    __syncthreads();

    // ---- pass 2: vertical blur + pointwise SSIM, strips of 8 rows ----
    // 256 strips = 64 cols * 4 row-groups.
    const float C1 = 0.01f * 0.01f;
    const float C2 = 0.03f * 0.03f;
    float acc = 0.f;
    if (tid < TX * (TY / 8)) {
        int c  = tid & (TX - 1);
        int rs = (tid >> 6) * 8;
        const float* q = H + rs * HP + c;

        float b0[8], b1[8], b2[8], b3[8], b4[8];
        #pragma unroll
        for (int o = 0; o < 8; o++) { b0[o]=0.f; b1[o]=0.f; b2[o]=0.f; b3[o]=0.f; b4[o]=0.f; }

        #pragma unroll
        for (int e = 0; e < 18; e++) {
            float f0 = q[0*HCH + e*HP];
            float f1 = q[1*HCH + e*HP];
            float f2 = q[2*HCH + e*HP];
            float f3 = q[3*HCH + e*HP];
            float f4 = q[4*HCH + e*HP];
            const int olo = (e >= 10) ? (e - 10) : 0;
            const int ohi = (e < 8) ? e : 7;
            #pragma unroll
            for (int o = olo; o <= ohi; o++) {
                const float w = Wt[e - o];
                b0[o] = fmaf(w, f0, b0[o]);
                b1[o] = fmaf(w, f1, b1[o]);
                b2[o] = fmaf(w, f2, b2[o]);
                b3[o] = fmaf(w, f3, b3[o]);
                b4[o] = fmaf(w, f4, b4[o]);
            }
        }
        #pragma unroll
        for (int o = 0; o < 8; o++) {
            float mu1 = b0[o], mu2 = b1[o];
            float mu1sq = mu1 * mu1;
            float mu2sq = mu2 * mu2;
            float mu12  = mu1 * mu2;
            float sg1  = b2[o] - mu1sq;
            float sg2  = b3[o] - mu2sq;
            float sg12 = b4[o] - mu12;
            float num = (2.0f * mu12 + C1) * (2.0f * sg12 + C2);
            float den = (mu1sq + mu2sq + C1) * (sg1 + sg2 + C2);
            acc += __fdividef(num, den);
        }
    }

    // ---- block reduction (deterministic) ----
    #pragma unroll
    for (int off = 16; off > 0; off >>= 1)
        acc += __shfl_xor_sync(0xFFFFFFFFu, acc, off);

    __shared__ float warpsum[NT / 32];
    if ((tid & 31) == 0) warpsum[tid >> 5] = acc;
    __syncthreads();
    if (tid == 0) {
        float s = 0.f;
        #pragma unroll
        for (int i = 0; i < NT / 32; i++) s += warpsum[i];
        int bid = blockIdx.x + GXB * (blockIdx.y + GYB * blockIdx.z);
        ((float*)g_partials4)[bid] = s;
    }
}

__global__ void ssim_finalize_kernel(float* __restrict__ out)
{
    __shared__ double sd[512];
    const int t = threadIdx.x;
    double s = 0.0;
    #pragma unroll
    for (int k = 0; k < NBLOCKS / 4 / 512; k++) {
        float4 v = g_partials4[t + k * 512];
        s += (double)v.x + (double)v.y + (double)v.z + (double)v.w;
    }
    sd[t] = s;
    __syncthreads();
    #pragma unroll
    for (int st = 256; st > 0; st >>= 1) {
        if (t < st) sd[t] += sd[t + st];
        __syncthreads();
    }
    if (t == 0) {
        const double N = 16.0 * 3.0 * 512.0 * 512.0;
        out[0] = (float)(1.0 - sd[0] / N);
    }
}

extern "C" void kernel_launch(void* const* d_in, const int* in_sizes, int n_in,
                              void* d_out, int out_size)
{
    const float* img1 = (const float*)d_in[0];
    const float* img2 = (const float*)d_in[1];
    float* out = (float*)d_out;

    const int smem_bytes = (2 * IH * IWP + 5 * IH * HP) * (int)sizeof(float); // 79800
    cudaFuncSetAttribute(ssim_tile_kernel,
                         cudaFuncAttributeMaxDynamicSharedMemorySize, smem_bytes);

    dim3 grid(GXB, GYB, NIMG);
    ssim_tile_kernel<<<grid, NT, smem_bytes>>>(img1, img2);
    ssim_finalize_kernel<<<1, 512>>>(out);
}